// round 7
// baseline (speedup 1.0000x reference)
#include <cuda_runtime.h>
#include <cuda_bf16.h>
#include <stdint.h>

// ---------------- problem constants ----------------
constexpr int Sdim = 2048, Hdim = 16, BHdim = 64, Ddim = 64;
constexpr int TQ = 64;            // query rows per CTA
constexpr int NK = 64;            // key slab
constexpr int NSLAB = Sdim / NK;  // 32

// ---------------- smem layout (byte offsets) ----------------
// bf16 tile rows: 72 elems = 144 B (16B aligned, ldmatrix conflict-free)
constexpr int RS_B    = 0;       // f32[64]
constexpr int INV_B   = 256;     // f32[64]
constexpr int PM_B    = 512;     // int[64]
constexpr int QS_HI_B = 1024;    // [64][72] bf16 = 9216 each
constexpr int QS_LO_B = 10240;
constexpr int KS_HI_B = 19456;
constexpr int KS_LO_B = 28672;
constexpr int VS_HI_B = 37888;
constexpr int VS_LO_B = 47104;
constexpr int PS_HI_B = 56320;
constexpr int PS_LO_B = 65536;
constexpr int SMEM_TOTAL = 74752;   // ~73 KB -> 2 CTAs/SM
constexpr int TSTR = 144;           // bytes per bf16 tile row

// ---------------- helpers ----------------
__device__ __forceinline__ uint32_t smem_u32(const void* p) {
    uint32_t a;
    asm("{ .reg .u64 t; cvta.to.shared.u64 t, %1; cvt.u32.u64 %0, t; }" : "=r"(a) : "l"(p));
    return a;
}
__device__ __forceinline__ void ldsm4(uint32_t addr, uint32_t& r0, uint32_t& r1,
                                      uint32_t& r2, uint32_t& r3) {
    asm volatile("ldmatrix.sync.aligned.m8n8.x4.shared.b16 {%0,%1,%2,%3}, [%4];"
                 : "=r"(r0), "=r"(r1), "=r"(r2), "=r"(r3) : "r"(addr));
}
__device__ __forceinline__ void ldsm4t(uint32_t addr, uint32_t& r0, uint32_t& r1,
                                       uint32_t& r2, uint32_t& r3) {
    asm volatile("ldmatrix.sync.aligned.m8n8.x4.trans.shared.b16 {%0,%1,%2,%3}, [%4];"
                 : "=r"(r0), "=r"(r1), "=r"(r2), "=r"(r3) : "r"(addr));
}
__device__ __forceinline__ void mma16816(float* c, uint32_t a0, uint32_t a1,
                                         uint32_t a2, uint32_t a3,
                                         uint32_t b0, uint32_t b1) {
    asm volatile(
        "mma.sync.aligned.m16n8k16.row.col.f32.bf16.bf16.f32 "
        "{%0,%1,%2,%3}, {%4,%5,%6,%7}, {%8,%9}, {%0,%1,%2,%3};"
        : "+f"(c[0]), "+f"(c[1]), "+f"(c[2]), "+f"(c[3])
        : "r"(a0), "r"(a1), "r"(a2), "r"(a3), "r"(b0), "r"(b1));
}
__device__ __forceinline__ void split2(char* hiB, char* loB, int off, float a, float b) {
    __nv_bfloat16 ah = __float2bfloat16_rn(a);
    __nv_bfloat16 bh = __float2bfloat16_rn(b);
    __nv_bfloat16 al = __float2bfloat16_rn(a - __bfloat162float(ah));
    __nv_bfloat16 bl = __float2bfloat16_rn(b - __bfloat162float(bh));
    *(__nv_bfloat162*)(hiB + off) = __halves2bfloat162(ah, bh);
    *(__nv_bfloat162*)(loB + off) = __halves2bfloat162(al, bl);
}

__global__ __launch_bounds__(256, 2)
void attn_fused(const float* __restrict__ Q, const float* __restrict__ K,
                const float* __restrict__ V, const int* __restrict__ pad,
                float* __restrict__ outO, float* __restrict__ outW)
{
    extern __shared__ __align__(16) char sm[];
    const int tid  = threadIdx.x;
    const int wid  = tid >> 5;
    const int lane = tid & 31;
    const int bh   = blockIdx.y;
    const int q0   = blockIdx.x * TQ;
    const int b    = bh / Hdim;

    const uint32_t smb = smem_u32(sm);
    float* rowsum = (float*)(sm + RS_B);
    float* invp   = (float*)(sm + INV_B);
    int*   pmp    = (int*)(sm + PM_B);

    const float* Qb = Q + ((size_t)bh * Sdim + q0) * Ddim;
    const float* Kb = K + (size_t)bh * Sdim * Ddim;
    const float* Vb = V + (size_t)bh * Sdim * Ddim;
    const int*   pb = pad + (size_t)b * Sdim;
    float* Wb = outW + ((size_t)bh * Sdim + q0) * Sdim;   // [TQ][Sdim]

    // ---- stage Q tile (bf16 hi/lo split), zero rowsums ----
    for (int i = tid; i < TQ * Ddim / 4; i += 256) {
        int q = i >> 4, db = (i & 15) * 4;
        float4 v = *(const float4*)(Qb + (size_t)q * Ddim + db);
        int base = q * TSTR + db * 2;
        split2(sm + QS_HI_B, sm + QS_LO_B, base,     v.x, v.y);
        split2(sm + QS_HI_B, sm + QS_LO_B, base + 4, v.z, v.w);
    }
    if (tid < TQ) rowsum[tid] = 0.f;
    __syncthreads();

    // warp tiles: wq = q-group (16 rows), wk = k/d-group (32 cols)
    const int wq = wid & 3;
    const int wk = wid >> 2;

    // ldmatrix lane->address components
    const int arow  = lane & 15;
    const int apart = (lane >> 4) * 16;
    const int brow  = (lane & 7) + ((lane >> 4) << 3);
    const int bpart = ((lane >> 3) & 1) * 16;
    const int vrow  = (lane & 7) + (((lane >> 3) & 1) << 3);
    const int vpart = (lane >> 4) * 16;

    const int rlo = wq * 16 + (lane >> 2);
    float rs_lo = 0.f, rs_hi = 0.f;

    // ---- hoist Q A-fragments (constant across slabs) ----
    uint32_t aH[4][4], aL[4][4];
    #pragma unroll
    for (int ks = 0; ks < 4; ++ks) {
        ldsm4(smb + QS_HI_B + (wq * 16 + arow) * TSTR + ks * 32 + apart,
              aH[ks][0], aH[ks][1], aH[ks][2], aH[ks][3]);
        ldsm4(smb + QS_LO_B + (wq * 16 + arow) * TSTR + ks * 32 + apart,
              aL[ks][0], aL[ks][1], aL[ks][2], aL[ks][3]);
    }

    // persistent PV accumulators (unnormalized)
    float co[4][4];
    #pragma unroll
    for (int n = 0; n < 4; ++n)
        #pragma unroll
        for (int j = 0; j < 4; ++j) co[n][j] = 0.f;

    const int qglo = q0 + rlo, qghi = qglo + 8;

    // ======================= fused mainloop =======================
    for (int s = 0; s < NSLAB; ++s) {
        const int k0 = s * NK;
        __syncthreads();   // prev slab's PV frag reads done; K/V/PS free

        // stage K + V slabs (bf16 hi/lo split) + padding mask
        for (int i = tid; i < NK * Ddim / 4; i += 256) {   // 1024 float4 (K)
            int k = i >> 4, db = (i & 15) * 4;
            float4 v = *(const float4*)(Kb + (size_t)(k0 + k) * Ddim + db);
            int base = k * TSTR + db * 2;
            split2(sm + KS_HI_B, sm + KS_LO_B, base,     v.x, v.y);
            split2(sm + KS_HI_B, sm + KS_LO_B, base + 4, v.z, v.w);
        }
        for (int i = tid; i < NK * Ddim / 4; i += 256) {   // 1024 float4 (V)
            int k = i >> 4, db = (i & 15) * 4;
            float4 v = *(const float4*)(Vb + (size_t)(k0 + k) * Ddim + db);
            int base = k * TSTR + db * 2;
            split2(sm + VS_HI_B, sm + VS_LO_B, base,     v.x, v.y);
            split2(sm + VS_HI_B, sm + VS_LO_B, base + 4, v.z, v.w);
        }
        if (tid < NK) pmp[tid] = pb[k0 + tid];
        __syncthreads();

        // ---- QK^T: 3 passes (hiQ*hiK, hiQ*loK, loQ*hiK) ----
        float c[4][4];
        #pragma unroll
        for (int n = 0; n < 4; ++n)
            #pragma unroll
            for (int j = 0; j < 4; ++j) c[n][j] = 0.f;

        #pragma unroll
        for (int p = 0; p < 3; ++p) {
            const uint32_t Bbuf = smb + ((p == 1) ? KS_LO_B : KS_HI_B);
            #pragma unroll
            for (int ks = 0; ks < 4; ++ks) {
                const uint32_t* a = (p < 2) ? aH[ks] : aL[ks];
                #pragma unroll
                for (int nt2 = 0; nt2 < 2; ++nt2) {
                    uint32_t b0, b1, b2, b3;
                    ldsm4(Bbuf + (wk * 32 + nt2 * 16 + brow) * TSTR + ks * 32 + bpart,
                          b0, b1, b2, b3);
                    mma16816(c[2 * nt2],     a[0], a[1], a[2], a[3], b0, b1);
                    mma16816(c[2 * nt2 + 1], a[0], a[1], a[2], a[3], b2, b3);
                }
            }
        }

        // ---- epilogue: mask/exp, rowsum, W store (unnorm), split -> PS ----
        #pragma unroll
        for (int nt = 0; nt < 4; ++nt) {
            const int col = wk * 32 + nt * 8 + (lane & 3) * 2;
            const int kg  = k0 + col;
            const int p0 = pmp[col], p1 = pmp[col + 1];
            float e0 = (((kg     > qglo) + p0) == 1) ? 0.f : __expf(c[nt][0] * 0.125f);
            float e1 = (((kg + 1 > qglo) + p1) == 1) ? 0.f : __expf(c[nt][1] * 0.125f);
            float e2 = (((kg     > qghi) + p0) == 1) ? 0.f : __expf(c[nt][2] * 0.125f);
            float e3 = (((kg + 1 > qghi) + p1) == 1) ? 0.f : __expf(c[nt][3] * 0.125f);
            rs_lo += e0 + e1;
            rs_hi += e2 + e3;
            *(float2*)&Wb[(size_t)rlo * Sdim + kg]       = make_float2(e0, e1);
            *(float2*)&Wb[(size_t)(rlo + 8) * Sdim + kg] = make_float2(e2, e3);
            split2(sm + PS_HI_B, sm + PS_LO_B, rlo * TSTR + col * 2,       e0, e1);
            split2(sm + PS_HI_B, sm + PS_LO_B, (rlo + 8) * TSTR + col * 2, e2, e3);
        }
        __syncthreads();   // PS columns span both wk warps -> block-level sync required

        // ---- PV accumulate: 3 passes (hiP*hiV, hiP*loV, loP*hiV) ----
        #pragma unroll
        for (int p = 0; p < 3; ++p) {
            const uint32_t Abuf = smb + ((p < 2) ? PS_HI_B : PS_LO_B);
            const uint32_t Bbuf = smb + ((p == 1) ? VS_LO_B : VS_HI_B);
            #pragma unroll
            for (int ks = 0; ks < 4; ++ks) {
                uint32_t a0, a1, a2, a3;
                ldsm4(Abuf + (wq * 16 + arow) * TSTR + ks * 32 + apart, a0, a1, a2, a3);
                #pragma unroll
                for (int nt2 = 0; nt2 < 2; ++nt2) {
                    uint32_t b0, b1, b2, b3;
                    ldsm4t(Bbuf + (ks * 16 + vrow) * TSTR + (wk * 32 + nt2 * 16) * 2 + vpart,
                           b0, b1, b2, b3);
                    mma16816(co[2 * nt2],     a0, a1, a2, a3, b0, b1);
                    mma16816(co[2 * nt2 + 1], a0, a1, a2, a3, b2, b3);
                }
            }
        }
    }

    // ---- rowsums -> inv ----
    rs_lo += __shfl_xor_sync(0xffffffffu, rs_lo, 1);
    rs_lo += __shfl_xor_sync(0xffffffffu, rs_lo, 2);
    rs_hi += __shfl_xor_sync(0xffffffffu, rs_hi, 1);
    rs_hi += __shfl_xor_sync(0xffffffffu, rs_hi, 2);
    if ((lane & 3) == 0) {
        atomicAdd(&rowsum[rlo], rs_lo);
        atomicAdd(&rowsum[rlo + 8], rs_hi);
    }
    __syncthreads();
    if (tid < TQ) invp[tid] = 1.0f / rowsum[tid];
    __syncthreads();

    // ---- O store (normalize accumulators) ----
    {
        const float ivlo = invp[rlo], ivhi = invp[rlo + 8];
        #pragma unroll
        for (int nt = 0; nt < 4; ++nt) {
            const int col = wk * 32 + nt * 8 + (lane & 3) * 2;
            const size_t r0o = ((size_t)bh * Sdim + q0 + rlo) * Ddim + col;
            const size_t r1o = ((size_t)bh * Sdim + q0 + rlo + 8) * Ddim + col;
            *(float2*)&outO[r0o] = make_float2(co[nt][0] * ivlo, co[nt][1] * ivlo);
            *(float2*)&outO[r1o] = make_float2(co[nt][2] * ivhi, co[nt][3] * ivhi);
        }
    }

    // ---- W normalize sweep (read unnorm e, scale, write final) ----
    for (int i = tid; i < TQ * (Sdim / 4); i += 256) {
        int q = i >> 9, c4 = (i & 511) * 4;
        float* gw = Wb + (size_t)q * Sdim + c4;
        float4 e = *(float4*)gw;
        const float iv = invp[q];
        e.x *= iv; e.y *= iv; e.z *= iv; e.w *= iv;
        *(float4*)gw = e;
    }
}

extern "C" void kernel_launch(void* const* d_in, const int* in_sizes, int n_in,
                              void* d_out, int out_size)
{
    const float* Q   = (const float*)d_in[0];
    const float* K   = (const float*)d_in[1];
    const float* V   = (const float*)d_in[2];
    const int*   pad = (const int*)d_in[3];

    const long long nres = (long long)BHdim * Sdim * Ddim;
    float* outO = (float*)d_out;
    float* outW = outO + nres;   // out = (result, attention_weights)

    cudaFuncSetAttribute(attn_fused, cudaFuncAttributeMaxDynamicSharedMemorySize, SMEM_TOTAL);

    dim3 grid(Sdim / TQ, BHdim);
    attn_fused<<<grid, 256, SMEM_TOTAL>>>(Q, K, V, pad, outO, outW);
}

// round 8
// speedup vs baseline: 1.5990x; 1.5990x over previous
#include <cuda_runtime.h>
#include <cuda_bf16.h>
#include <stdint.h>

// ---------------- problem constants ----------------
constexpr int Sdim = 2048, Hdim = 16, BHdim = 64, Ddim = 64;
constexpr int TQ = 64;            // query rows per CTA
constexpr int NK = 64;            // key slab
constexpr int NSLAB = Sdim / NK;  // 32

constexpr int TSTR = 144;         // bytes per bf16 tile row (64+8 elems, ldmatrix conflict-free)
constexpr int TILE_B = NK * TSTR;            // 9216 per tile part
constexpr int SLAB_B = 4 * TILE_B;           // KS_HI|KS_LO|VS_HI|VS_LO = 36864
// pre-tiled K/V scratch: [bh][slab][4 tiles]
__device__ __align__(16) unsigned char g_kv[(size_t)BHdim * NSLAB * SLAB_B];

// ---------------- smem layout (byte offsets) ----------------
constexpr int RS_B    = 0;        // f32[64]
constexpr int INV_B   = 256;      // f32[64]
constexpr int PM_B    = 512;      // int[2][64] double-buffered pad mask
constexpr int QS_HI_B = 1024;     // [64][72] bf16 = 9216 each
constexpr int QS_LO_B = 10240;
constexpr int KV0_B   = 19456;    // double-buffered slab: 2 x 36864
constexpr int PS_HI_B = 93184;
constexpr int PS_LO_B = 102400;
constexpr int SMEM_TOTAL = 111616;   // 109 KB -> 2 CTAs/SM (218KB)

// ---------------- helpers ----------------
__device__ __forceinline__ uint32_t smem_u32(const void* p) {
    uint32_t a;
    asm("{ .reg .u64 t; cvta.to.shared.u64 t, %1; cvt.u32.u64 %0, t; }" : "=r"(a) : "l"(p));
    return a;
}
__device__ __forceinline__ void cp16(uint32_t sdst, const void* gsrc) {
    asm volatile("cp.async.cg.shared.global [%0], [%1], 16;" :: "r"(sdst), "l"(gsrc));
}
__device__ __forceinline__ void ldsm4(uint32_t addr, uint32_t& r0, uint32_t& r1,
                                      uint32_t& r2, uint32_t& r3) {
    asm volatile("ldmatrix.sync.aligned.m8n8.x4.shared.b16 {%0,%1,%2,%3}, [%4];"
                 : "=r"(r0), "=r"(r1), "=r"(r2), "=r"(r3) : "r"(addr));
}
__device__ __forceinline__ void ldsm4t(uint32_t addr, uint32_t& r0, uint32_t& r1,
                                       uint32_t& r2, uint32_t& r3) {
    asm volatile("ldmatrix.sync.aligned.m8n8.x4.trans.shared.b16 {%0,%1,%2,%3}, [%4];"
                 : "=r"(r0), "=r"(r1), "=r"(r2), "=r"(r3) : "r"(addr));
}
__device__ __forceinline__ void mma16816(float* c, uint32_t a0, uint32_t a1,
                                         uint32_t a2, uint32_t a3,
                                         uint32_t b0, uint32_t b1) {
    asm volatile(
        "mma.sync.aligned.m16n8k16.row.col.f32.bf16.bf16.f32 "
        "{%0,%1,%2,%3}, {%4,%5,%6,%7}, {%8,%9}, {%0,%1,%2,%3};"
        : "+f"(c[0]), "+f"(c[1]), "+f"(c[2]), "+f"(c[3])
        : "r"(a0), "r"(a1), "r"(a2), "r"(a3), "r"(b0), "r"(b1));
}
__device__ __forceinline__ void split2(char* hiB, char* loB, int off, float a, float b) {
    __nv_bfloat16 ah = __float2bfloat16_rn(a);
    __nv_bfloat16 bh = __float2bfloat16_rn(b);
    __nv_bfloat16 al = __float2bfloat16_rn(a - __bfloat162float(ah));
    __nv_bfloat16 bl = __float2bfloat16_rn(b - __bfloat162float(bh));
    *(__nv_bfloat162*)(hiB + off) = __halves2bfloat162(ah, bh);
    *(__nv_bfloat162*)(loB + off) = __halves2bfloat162(al, bl);
}

// ================= preprocessing: K,V fp32 -> tiled bf16 hi/lo =================
__global__ __launch_bounds__(256)
void prep_kv(const float* __restrict__ K, const float* __restrict__ V)
{
    const int s  = blockIdx.x;
    const int bh = blockIdx.y;
    const int tid = threadIdx.x;
    const float* Kb = K + ((size_t)bh * Sdim + s * NK) * Ddim;
    const float* Vb = V + ((size_t)bh * Sdim + s * NK) * Ddim;
    char* dst = (char*)g_kv + ((size_t)bh * NSLAB + s) * SLAB_B;

    for (int i = tid; i < NK * Ddim / 4; i += 256) {   // 1024 float4 each
        int k = i >> 4, db = (i & 15) * 4;
        int off = k * TSTR + db * 2;
        float4 kv4 = *(const float4*)(Kb + (size_t)k * Ddim + db);
        split2(dst,              dst + TILE_B,     off,     kv4.x, kv4.y);
        split2(dst,              dst + TILE_B,     off + 4, kv4.z, kv4.w);
        float4 vv4 = *(const float4*)(Vb + (size_t)k * Ddim + db);
        split2(dst + 2 * TILE_B, dst + 3 * TILE_B, off,     vv4.x, vv4.y);
        split2(dst + 2 * TILE_B, dst + 3 * TILE_B, off + 4, vv4.z, vv4.w);
    }
}

// ================= fused attention =================
__global__ __launch_bounds__(256, 2)
void attn_fused(const float* __restrict__ Q, const int* __restrict__ pad,
                float* __restrict__ outO, float* __restrict__ outW)
{
    extern __shared__ __align__(16) char sm[];
    const int tid  = threadIdx.x;
    const int wid  = tid >> 5;
    const int lane = tid & 31;
    const int bh   = blockIdx.y;
    const int q0   = blockIdx.x * TQ;
    const int b    = bh / Hdim;

    const uint32_t smb = smem_u32(sm);
    float* rowsum = (float*)(sm + RS_B);
    float* invp   = (float*)(sm + INV_B);
    int*   pmp    = (int*)(sm + PM_B);     // [2][64]

    const float* Qb = Q + ((size_t)bh * Sdim + q0) * Ddim;
    const int*   pb = pad + (size_t)b * Sdim;
    const char*  Gkv = (const char*)g_kv + (size_t)bh * NSLAB * SLAB_B;
    float* Wb = outW + ((size_t)bh * Sdim + q0) * Sdim;   // [TQ][Sdim]

    // ---- prologue: stage Q (bf16 hi/lo), kick slab-0 copy, pad[0] ----
    for (int i = tid; i < TQ * Ddim / 4; i += 256) {
        int q = i >> 4, db = (i & 15) * 4;
        float4 v = *(const float4*)(Qb + (size_t)q * Ddim + db);
        int base = q * TSTR + db * 2;
        split2(sm + QS_HI_B, sm + QS_LO_B, base,     v.x, v.y);
        split2(sm + QS_HI_B, sm + QS_LO_B, base + 4, v.z, v.w);
    }
    #pragma unroll
    for (int i = 0; i < SLAB_B / 16 / 256; ++i)   // 9 chunks/thread
        cp16(smb + KV0_B + (tid + i * 256) * 16, Gkv + (tid + i * 256) * 16);
    asm volatile("cp.async.commit_group;" ::: "memory");
    if (tid < NK) pmp[tid] = pb[tid];
    if (tid < TQ) rowsum[tid] = 0.f;
    __syncthreads();

    // warp tiles: wq = q-group (16 rows), wk = k/d-group (32 cols)
    const int wq = wid & 3;
    const int wk = wid >> 2;
    const int arow  = lane & 15;
    const int apart = (lane >> 4) * 16;
    const int brow  = (lane & 7) + ((lane >> 4) << 3);
    const int bpart = ((lane >> 3) & 1) * 16;
    const int vrow  = (lane & 7) + (((lane >> 3) & 1) << 3);
    const int vpart = (lane >> 4) * 16;
    const int rlo = wq * 16 + (lane >> 2);
    float rs_lo = 0.f, rs_hi = 0.f;

    // hoist Q A-fragments (constant across slabs)
    uint32_t aH[4][4], aL[4][4];
    #pragma unroll
    for (int ks = 0; ks < 4; ++ks) {
        ldsm4(smb + QS_HI_B + (wq * 16 + arow) * TSTR + ks * 32 + apart,
              aH[ks][0], aH[ks][1], aH[ks][2], aH[ks][3]);
        ldsm4(smb + QS_LO_B + (wq * 16 + arow) * TSTR + ks * 32 + apart,
              aL[ks][0], aL[ks][1], aL[ks][2], aL[ks][3]);
    }

    float co[4][4];
    #pragma unroll
    for (int n = 0; n < 4; ++n)
        #pragma unroll
        for (int j = 0; j < 4; ++j) co[n][j] = 0.f;

    const int qglo = q0 + rlo, qghi = qglo + 8;

    // ======================= mainloop =======================
    for (int s = 0; s < NSLAB; ++s) {
        const int buf = s & 1;
        const uint32_t KV = smb + KV0_B + buf * SLAB_B;

        asm volatile("cp.async.wait_group 0;" ::: "memory");
        __syncthreads();   // slab s data visible to all; prev readers of buf^1 done

        // kick next slab copy + pad mask into the other buffer
        if (s + 1 < NSLAB) {
            const char* gsrc = Gkv + (size_t)(s + 1) * SLAB_B;
            const uint32_t sdst = smb + KV0_B + (buf ^ 1) * SLAB_B;
            #pragma unroll
            for (int i = 0; i < SLAB_B / 16 / 256; ++i)
                cp16(sdst + (tid + i * 256) * 16, gsrc + (tid + i * 256) * 16);
            asm volatile("cp.async.commit_group;" ::: "memory");
            if (tid < NK) pmp[(buf ^ 1) * 64 + tid] = pb[(s + 1) * NK + tid];
        }

        // ---- QK^T: 3 passes (hiQ*hiK, hiQ*loK, loQ*hiK) ----
        float c[4][4];
        #pragma unroll
        for (int n = 0; n < 4; ++n)
            #pragma unroll
            for (int j = 0; j < 4; ++j) c[n][j] = 0.f;

        #pragma unroll
        for (int p = 0; p < 3; ++p) {
            const uint32_t Bbuf = KV + ((p == 1) ? TILE_B : 0);
            #pragma unroll
            for (int ks = 0; ks < 4; ++ks) {
                const uint32_t* a = (p < 2) ? aH[ks] : aL[ks];
                #pragma unroll
                for (int nt2 = 0; nt2 < 2; ++nt2) {
                    uint32_t b0, b1, b2, b3;
                    ldsm4(Bbuf + (wk * 32 + nt2 * 16 + brow) * TSTR + ks * 32 + bpart,
                          b0, b1, b2, b3);
                    mma16816(c[2 * nt2],     a[0], a[1], a[2], a[3], b0, b1);
                    mma16816(c[2 * nt2 + 1], a[0], a[1], a[2], a[3], b2, b3);
                }
            }
        }

        // ---- epilogue: mask/exp, rowsum, W store (unnorm), split -> PS ----
        const int* pmb = pmp + buf * 64;
        const int k0 = s * NK;
        #pragma unroll
        for (int nt = 0; nt < 4; ++nt) {
            const int col = wk * 32 + nt * 8 + (lane & 3) * 2;
            const int kg  = k0 + col;
            const int p0 = pmb[col], p1 = pmb[col + 1];
            float e0 = (((kg     > qglo) + p0) == 1) ? 0.f : __expf(c[nt][0] * 0.125f);
            float e1 = (((kg + 1 > qglo) + p1) == 1) ? 0.f : __expf(c[nt][1] * 0.125f);
            float e2 = (((kg     > qghi) + p0) == 1) ? 0.f : __expf(c[nt][2] * 0.125f);
            float e3 = (((kg + 1 > qghi) + p1) == 1) ? 0.f : __expf(c[nt][3] * 0.125f);
            rs_lo += e0 + e1;
            rs_hi += e2 + e3;
            *(float2*)&Wb[(size_t)rlo * Sdim + kg]       = make_float2(e0, e1);
            *(float2*)&Wb[(size_t)(rlo + 8) * Sdim + kg] = make_float2(e2, e3);
            split2(sm + PS_HI_B, sm + PS_LO_B, rlo * TSTR + col * 2,       e0, e1);
            split2(sm + PS_HI_B, sm + PS_LO_B, (rlo + 8) * TSTR + col * 2, e2, e3);
        }
        __syncthreads();   // PS columns span both wk warps

        // ---- PV accumulate: 3 passes (hiP*hiV, hiP*loV, loP*hiV) ----
        #pragma unroll
        for (int p = 0; p < 3; ++p) {
            const uint32_t Abuf = smb + ((p < 2) ? PS_HI_B : PS_LO_B);
            const uint32_t Bbuf = KV + 2 * TILE_B + ((p == 1) ? TILE_B : 0);
            #pragma unroll
            for (int ks = 0; ks < 4; ++ks) {
                uint32_t a0, a1, a2, a3;
                ldsm4(Abuf + (wq * 16 + arow) * TSTR + ks * 32 + apart, a0, a1, a2, a3);
                #pragma unroll
                for (int nt2 = 0; nt2 < 2; ++nt2) {
                    uint32_t b0, b1, b2, b3;
                    ldsm4t(Bbuf + (ks * 16 + vrow) * TSTR + (wk * 32 + nt2 * 16) * 2 + vpart,
                           b0, b1, b2, b3);
                    mma16816(co[2 * nt2],     a0, a1, a2, a3, b0, b1);
                    mma16816(co[2 * nt2 + 1], a0, a1, a2, a3, b2, b3);
                }
            }
        }
    }

    // ---- rowsums -> inv ----
    rs_lo += __shfl_xor_sync(0xffffffffu, rs_lo, 1);
    rs_lo += __shfl_xor_sync(0xffffffffu, rs_lo, 2);
    rs_hi += __shfl_xor_sync(0xffffffffu, rs_hi, 1);
    rs_hi += __shfl_xor_sync(0xffffffffu, rs_hi, 2);
    if ((lane & 3) == 0) {
        atomicAdd(&rowsum[rlo], rs_lo);
        atomicAdd(&rowsum[rlo + 8], rs_hi);
    }
    __syncthreads();
    if (tid < TQ) invp[tid] = 1.0f / rowsum[tid];
    __syncthreads();

    // ---- O store (normalize accumulators) ----
    {
        const float ivlo = invp[rlo], ivhi = invp[rlo + 8];
        #pragma unroll
        for (int nt = 0; nt < 4; ++nt) {
            const int col = wk * 32 + nt * 8 + (lane & 3) * 2;
            const size_t r0o = ((size_t)bh * Sdim + q0 + rlo) * Ddim + col;
            const size_t r1o = ((size_t)bh * Sdim + q0 + rlo + 8) * Ddim + col;
            *(float2*)&outO[r0o] = make_float2(co[nt][0] * ivlo, co[nt][1] * ivlo);
            *(float2*)&outO[r1o] = make_float2(co[nt][2] * ivhi, co[nt][3] * ivhi);
        }
    }

    // ---- W normalize sweep ----
    for (int i = tid; i < TQ * (Sdim / 4); i += 256) {
        int q = i >> 9, c4 = (i & 511) * 4;
        float* gw = Wb + (size_t)q * Sdim + c4;
        float4 e = *(float4*)gw;
        const float iv = invp[q];
        e.x *= iv; e.y *= iv; e.z *= iv; e.w *= iv;
        *(float4*)gw = e;
    }
}

extern "C" void kernel_launch(void* const* d_in, const int* in_sizes, int n_in,
                              void* d_out, int out_size)
{
    const float* Q   = (const float*)d_in[0];
    const float* K   = (const float*)d_in[1];
    const float* V   = (const float*)d_in[2];
    const int*   pad = (const int*)d_in[3];

    const long long nres = (long long)BHdim * Sdim * Ddim;
    float* outO = (float*)d_out;
    float* outW = outO + nres;   // out = (result, attention_weights)

    dim3 pgrid(NSLAB, BHdim);
    prep_kv<<<pgrid, 256>>>(K, V);

    cudaFuncSetAttribute(attn_fused, cudaFuncAttributeMaxDynamicSharedMemorySize, SMEM_TOTAL);
    dim3 grid(Sdim / TQ, BHdim);
    attn_fused<<<grid, 256, SMEM_TOTAL>>>(Q, pad, outO, outW);
}